// round 11
// baseline (speedup 1.0000x reference)
#include <cuda_runtime.h>
#include <math.h>

#define N_MAX 100000
#define E_MAX 1600000
#define G_NUM 1024
#define SCAN_B 1024
#define NBLK_MAX 128   // ceil(100000/1024)=98

// ---------------- device scratch (no allocation allowed) -------------------
__device__ __align__(16) float g_B0[(long long)N_MAX * 64]; // ping
__device__ __align__(16) float g_B1[(long long)N_MAX * 64]; // pong
__device__ float g_dinv[N_MAX];
__device__ int   g_deg [N_MAX];
__device__ int   g_tmp [N_MAX];        // block-scan partials
__device__ int   g_off [N_MAX + 1];    // CSR offsets (by dst)
__device__ int   g_cur [N_MAX];        // fill cursors (seeded to g_off)
__device__ int   g_bsum[NBLK_MAX];     // block sums for scan
__device__ int   g_csrc[E_MAX];        // CSR src ids
__device__ float g_pool[G_NUM * 64];

__device__ __forceinline__ float* buf(int s) { return s == 0 ? g_B0 : g_B1; }

// ---------------------------- prep -----------------------------------------
__global__ void k_zero(int n) {
    int i = blockIdx.x * blockDim.x + threadIdx.x;
    if (i < n)          g_deg[i]  = 0;
    if (i < G_NUM * 64) g_pool[i] = 0.f;
}

__global__ void k_degcount(const int* __restrict__ ei, int E) {
    int e = blockIdx.x * blockDim.x + threadIdx.x;
    if (e < E) atomicAdd(&g_deg[ei[E + e]], 1);
}

// ------------------------- 3-kernel exclusive scan --------------------------
__global__ void k_scan1(int n) {
    __shared__ int s[SCAN_B];
    int t = threadIdx.x;
    int i = blockIdx.x * SCAN_B + t;
    int v = (i < n) ? g_deg[i] : 0;
    s[t] = v;
    __syncthreads();
#pragma unroll
    for (int d = 1; d < SCAN_B; d <<= 1) {
        int x = (t >= d) ? s[t - d] : 0;
        __syncthreads();
        s[t] += x;
        __syncthreads();
    }
    if (i < n) g_tmp[i] = s[t];                 // inclusive
    if (t == SCAN_B - 1) g_bsum[blockIdx.x] = s[t];
}

__global__ void k_scan2(int nblk) {
    __shared__ int s[NBLK_MAX];
    int t = threadIdx.x;
    int v = (t < nblk) ? g_bsum[t] : 0;
    s[t] = v;
    __syncthreads();
#pragma unroll
    for (int d = 1; d < NBLK_MAX; d <<= 1) {
        int x = (t >= d) ? s[t - d] : 0;
        __syncthreads();
        s[t] += x;
        __syncthreads();
    }
    if (t < nblk) g_bsum[t] = s[t] - v;         // exclusive
}

__global__ void k_scan3(int n, int E) {
    int i = blockIdx.x * blockDim.x + threadIdx.x;
    if (i < n) {
        int deg = g_deg[i];
        int off = g_tmp[i] - deg + g_bsum[i / SCAN_B];  // exclusive
        g_off[i] = off;
        g_cur[i] = off;
        g_dinv[i] = rsqrtf((float)(deg + 1));           // +1 self loop
    }
    if (i == 0) g_off[n] = E;
}

__global__ void k_fill(const int* __restrict__ ei, int E) {
    int e = blockIdx.x * blockDim.x + threadIdx.x;
    if (e >= E) return;
    int s = ei[e];
    int d = ei[E + e];
    int pos = atomicAdd(&g_cur[d], 1);
    g_csrc[pos] = s;
}

// ---------------------------------------------------------------------------
// Node transform: acc = in @ W, then epilogue:
//   EPI 0: out = acc * dinv                      (pre-scale for next gather)
//   EPI 1: out = relu(acc + b) * dinv            (activation + pre-scale)
//   EPI 2: out = relu(acc + b)                   (final features for pool)
// ---------------------------------------------------------------------------
template <int F_IN, int F_OUT, int EPI>
__global__ void k_transform(const float* __restrict__ x_ext, int in_sel, int out_sel,
                            const float* __restrict__ W,
                            const float* __restrict__ bout, int n)
{
    __shared__ float sW[F_IN * F_OUT];
    for (int i = threadIdx.x; i < F_IN * F_OUT; i += blockDim.x) sW[i] = W[i];
    __syncthreads();

    int node = blockIdx.x * blockDim.x + threadIdx.x;
    if (node >= n) return;

    const float* in = x_ext ? x_ext : buf(in_sel);
    const float4* row4 = reinterpret_cast<const float4*>(in) +
                         (long long)node * (F_IN / 4);

    float acc[F_OUT];
#pragma unroll
    for (int j = 0; j < F_OUT; j++) acc[j] = 0.f;

    for (int k4 = 0; k4 < F_IN / 4; k4++) {
        float4 v4 = row4[k4];
        float vv[4] = {v4.x, v4.y, v4.z, v4.w};
#pragma unroll
        for (int u = 0; u < 4; u++) {
            int k = k4 * 4 + u;
#pragma unroll
            for (int j = 0; j < F_OUT; j++)
                acc[j] = fmaf(vv[u], sW[k * F_OUT + j], acc[j]);
        }
    }

    float di = g_dinv[node];
    float4* out4 = reinterpret_cast<float4*>(buf(out_sel)) +
                   (long long)node * (F_OUT / 4);
#pragma unroll
    for (int j4 = 0; j4 < F_OUT / 4; j4++) {
        float o[4];
#pragma unroll
        for (int u = 0; u < 4; u++) {
            float a = acc[j4 * 4 + u];
            if (EPI == 0)      o[u] = a * di;
            else if (EPI == 1) o[u] = fmaxf(a + bout[j4 * 4 + u], 0.f) * di;
            else               o[u] = fmaxf(a + bout[j4 * 4 + u], 0.f);
        }
        out4[j4] = make_float4(o[0], o[1], o[2], o[3]);
    }
}

// ---------------------------------------------------------------------------
// Warp-per-node gather: m = dinv * ( in[d] + sum_{src->d} in[src] )
//   FUSED=false: out = m
//   FUSED=true : out = relu(m + b) * dinv
// 32 lanes = (32/L) edge slots x L float4-lanes; shfl cross-slot reduction.
// ---------------------------------------------------------------------------
template <int F, bool FUSED>
__global__ void k_gather(int in_sel, int out_sel,
                         const float* __restrict__ bias, int n)
{
    constexpr int L = F / 4;          // float4 lanes per node row
    constexpr int SLOTS = 32 / L;     // parallel edge slots per warp

    int node = blockIdx.x * blockDim.y + threadIdx.y;
    if (node >= n) return;
    int lane = threadIdx.x;
    int slot = lane / L;
    int f4   = lane % L;

    const float4* In4 = reinterpret_cast<const float4*>(buf(in_sel));
    int e0 = g_off[node];
    int e1 = g_off[node + 1];

    float4 a = make_float4(0.f, 0.f, 0.f, 0.f);
    if (slot == 0) a = In4[(long long)node * L + f4];   // self-loop term

    for (int e = e0 + slot; e < e1; e += SLOTS) {
        int s = g_csrc[e];
        float4 v = In4[(long long)s * L + f4];
        a.x += v.x; a.y += v.y; a.z += v.z; a.w += v.w;
    }

#pragma unroll
    for (int off = 16; off >= L; off >>= 1) {
        a.x += __shfl_xor_sync(0xffffffffu, a.x, off);
        a.y += __shfl_xor_sync(0xffffffffu, a.y, off);
        a.z += __shfl_xor_sync(0xffffffffu, a.z, off);
        a.w += __shfl_xor_sync(0xffffffffu, a.w, off);
    }

    if (slot == 0) {
        float di = g_dinv[node];
        float4 o;
        o.x = a.x * di; o.y = a.y * di; o.z = a.z * di; o.w = a.w * di;
        if (FUSED) {
            const float4 b4 = reinterpret_cast<const float4*>(bias)[f4];
            o.x = fmaxf(o.x + b4.x, 0.f) * di;
            o.y = fmaxf(o.y + b4.y, 0.f) * di;
            o.z = fmaxf(o.z + b4.z, 0.f) * di;
            o.w = fmaxf(o.w + b4.w, 0.f) * di;
        }
        reinterpret_cast<float4*>(buf(out_sel))[(long long)node * L + f4] = o;
    }
}

// ----------------- pool: segment max over sorted batch ids -----------------
__global__ void k_pool(int in_sel, const int* __restrict__ batch, int n)
{
    int f = threadIdx.x;                              // 0..63
    int chunk = blockIdx.x * blockDim.y + threadIdx.y;
    int n0 = chunk * 16;
    if (n0 >= n) return;
    int n1 = min(n0 + 16, n);
    const float* h = buf(in_sel);

    int curg = batch[n0];
    float m = h[(long long)n0 * 64 + f];
    for (int i = n0 + 1; i < n1; i++) {
        int g = batch[i];
        float v = h[(long long)i * 64 + f];
        if (g != curg) {
            atomicMax((unsigned int*)&g_pool[curg * 64 + f], __float_as_uint(m));
            curg = g;
            m = v;
        } else {
            m = fmaxf(m, v);
        }
    }
    atomicMax((unsigned int*)&g_pool[curg * 64 + f], __float_as_uint(m));
}

// ---------------- fused MLP head: 16 graphs per block -----------------------
// grid = 64 blocks x 256 threads. Weight traffic: 64x(65KB+262KB) ~ 21MB
// (vs 1024 blocks re-reading -> 335MB).
__global__ void k_mlp(const float* __restrict__ W1, const float* __restrict__ b1,
                      const float* __restrict__ W2, const float* __restrict__ b2,
                      float* __restrict__ out)
{
    __shared__ float sp[16 * 64];     // pooled rows for 16 graphs
    __shared__ float sz[16 * 256];    // hidden activations
    int j  = threadIdx.x;             // output feature 0..255
    int g0 = blockIdx.x * 16;

    for (int i = j; i < 16 * 64; i += 256)
        sp[i] = g_pool[g0 * 64 + i];
    __syncthreads();

    float z[16];
    float bb = b1[j];
#pragma unroll
    for (int gi = 0; gi < 16; gi++) z[gi] = bb;
    for (int k = 0; k < 64; k++) {
        float w = W1[k * 256 + j];
#pragma unroll
        for (int gi = 0; gi < 16; gi++)
            z[gi] = fmaf(sp[gi * 64 + k], w, z[gi]);
    }
#pragma unroll
    for (int gi = 0; gi < 16; gi++)
        sz[gi * 256 + j] = fmaxf(z[gi], 0.f);
    __syncthreads();

    float o[16];
    float bb2 = b2[j];
#pragma unroll
    for (int gi = 0; gi < 16; gi++) o[gi] = bb2;
    for (int k = 0; k < 256; k++) {
        float w = W2[k * 256 + j];
#pragma unroll
        for (int gi = 0; gi < 16; gi++)
            o[gi] = fmaf(sz[gi * 256 + k], w, o[gi]);
    }
#pragma unroll
    for (int gi = 0; gi < 16; gi++)
        out[(long long)(g0 + gi) * 256 + j] = 1.f / (1.f + expf(-o[gi]));
}

// ------------------------------ launch -------------------------------------
extern "C" void kernel_launch(void* const* d_in, const int* in_sizes, int n_in,
                              void* d_out, int out_size)
{
    const float* x     = (const float*)d_in[0];
    const int*   ei    = (const int*)d_in[1];    // int32 (JAX x64 disabled)
    const int*   batch = (const int*)d_in[2];
    const float* W1 = (const float*)d_in[3];
    const float* b1 = (const float*)d_in[4];
    const float* W2 = (const float*)d_in[5];
    const float* b2 = (const float*)d_in[6];
    const float* W3 = (const float*)d_in[7];
    const float* b3 = (const float*)d_in[8];
    const float* L1w = (const float*)d_in[9];
    const float* L1b = (const float*)d_in[10];
    const float* L2w = (const float*)d_in[11];
    const float* L2b = (const float*)d_in[12];
    float* out = (float*)d_out;

    int N = in_sizes[0] / 128;
    int E = in_sizes[1] / 2;
    int nblk = (N + SCAN_B - 1) / SCAN_B;

    // CSR build (by destination)
    k_zero    <<<(N + 255) / 256, 256>>>(N);
    k_degcount<<<(E + 255) / 256, 256>>>(ei, E);
    k_scan1   <<<nblk, SCAN_B>>>(N);
    k_scan2   <<<1, NBLK_MAX>>>(nblk);
    k_scan3   <<<(N + 255) / 256, 256>>>(N, E);
    k_fill    <<<(E + 255) / 256, 256>>>(ei, E);

    dim3 gb(32, 8);                       // warp-per-node gathers
    int ggrid = (N + 7) / 8;

    // Layer 1:  q0 = (x @ W1) * dinv                       [N,16] -> buf0
    k_transform<128, 16, 0><<<(N + 127) / 128, 128>>>(x, 0, 0, W1, nullptr, N);
    //           q1 = relu(dinv*(q0+Σq0) + b1) * dinv       [N,16] -> buf1
    k_gather<16, true ><<<ggrid, gb>>>(0, 1, b1, N);

    // Layer 2:  m2 = dinv*(q1+Σq1)                         [N,16] -> buf0
    k_gather<16, false><<<ggrid, gb>>>(1, 0, nullptr, N);
    //           q2 = relu(m2 @ W2 + b2) * dinv             [N,32] -> buf1
    k_transform<16, 32, 1><<<(N + 127) / 128, 128>>>(nullptr, 0, 1, W2, b2, N);

    // Layer 3:  m3 = dinv*(q2+Σq2)                         [N,32] -> buf0
    k_gather<32, false><<<ggrid, gb>>>(1, 0, nullptr, N);
    //           h3 = relu(m3 @ W3 + b3)                    [N,64] -> buf1
    k_transform<32, 64, 2><<<(N + 127) / 128, 128>>>(nullptr, 0, 1, W3, b3, N);

    // Pool (batch sorted) + fused MLP head
    { dim3 pb(64, 4); int chunks = (N + 15) / 16;
      k_pool<<<(chunks + 3) / 4, pb>>>(1, batch, N); }
    k_mlp<<<G_NUM / 16, 256>>>(L1w, L1b, L2w, L2b, out);
}

// round 12
// speedup vs baseline: 1.1632x; 1.1632x over previous
#include <cuda_runtime.h>
#include <math.h>

#define N_MAX 100000
#define E_MAX 1600000
#define G_NUM 1024
#define SCAN_B 1024
#define NBLK_MAX 128   // ceil(100000/1024)=98

// ---------------- device scratch (no allocation allowed) -------------------
__device__ __align__(16) float g_B0[(long long)N_MAX * 64]; // ping
__device__ __align__(16) float g_B1[(long long)N_MAX * 64]; // pong
__device__ float g_dinv[N_MAX];
__device__ int   g_deg [N_MAX];
__device__ int   g_tmp [N_MAX];        // block-scan partials
__device__ int   g_off [N_MAX + 1];    // CSR offsets (by dst)
__device__ int   g_cur [N_MAX];        // fill cursors (seeded to g_off)
__device__ int   g_bsum[NBLK_MAX];     // block sums for scan
__device__ int   g_csrc[E_MAX];        // CSR src ids
__device__ float g_pool[G_NUM * 64];

__device__ __forceinline__ float* buf(int s) { return s == 0 ? g_B0 : g_B1; }

// ---------------------------- prep -----------------------------------------
__global__ void k_zero(int n) {
    int i = blockIdx.x * blockDim.x + threadIdx.x;
    if (i < n)          g_deg[i]  = 0;
    if (i < G_NUM * 64) g_pool[i] = 0.f;
}

__global__ void k_degcount(const int* __restrict__ ei, int E) {
    int e = blockIdx.x * blockDim.x + threadIdx.x;
    if (e < E) atomicAdd(&g_deg[ei[E + e]], 1);
}

// ------------------------- 3-kernel exclusive scan --------------------------
__global__ void k_scan1(int n) {
    __shared__ int s[SCAN_B];
    int t = threadIdx.x;
    int i = blockIdx.x * SCAN_B + t;
    int v = (i < n) ? g_deg[i] : 0;
    s[t] = v;
    __syncthreads();
#pragma unroll
    for (int d = 1; d < SCAN_B; d <<= 1) {
        int x = (t >= d) ? s[t - d] : 0;
        __syncthreads();
        s[t] += x;
        __syncthreads();
    }
    if (i < n) g_tmp[i] = s[t];                 // inclusive
    if (t == SCAN_B - 1) g_bsum[blockIdx.x] = s[t];
}

__global__ void k_scan2(int nblk) {
    __shared__ int s[NBLK_MAX];
    int t = threadIdx.x;
    int v = (t < nblk) ? g_bsum[t] : 0;
    s[t] = v;
    __syncthreads();
#pragma unroll
    for (int d = 1; d < NBLK_MAX; d <<= 1) {
        int x = (t >= d) ? s[t - d] : 0;
        __syncthreads();
        s[t] += x;
        __syncthreads();
    }
    if (t < nblk) g_bsum[t] = s[t] - v;         // exclusive
}

__global__ void k_scan3(int n, int E) {
    int i = blockIdx.x * blockDim.x + threadIdx.x;
    if (i < n) {
        int deg = g_deg[i];
        int off = g_tmp[i] - deg + g_bsum[i / SCAN_B];  // exclusive
        g_off[i] = off;
        g_cur[i] = off;
        g_dinv[i] = rsqrtf((float)(deg + 1));           // +1 self loop
    }
    if (i == 0) g_off[n] = E;
}

__global__ void k_fill(const int* __restrict__ ei, int E) {
    int e = blockIdx.x * blockDim.x + threadIdx.x;
    if (e >= E) return;
    int s = ei[e];
    int d = ei[E + e];
    int pos = atomicAdd(&g_cur[d], 1);
    g_csrc[pos] = s;
}

// ---------------------------------------------------------------------------
// Node transform: acc = in @ W, then epilogue:
//   EPI 0: out = acc * dinv                      (pre-scale for next gather)
//   EPI 1: out = relu(acc + b) * dinv            (activation + pre-scale)
//   EPI 2: out = relu(acc + b)                   (final features for pool)
// ---------------------------------------------------------------------------
template <int F_IN, int F_OUT, int EPI>
__global__ void k_transform(const float* __restrict__ x_ext, int in_sel, int out_sel,
                            const float* __restrict__ W,
                            const float* __restrict__ bout, int n)
{
    __shared__ float sW[F_IN * F_OUT];
    for (int i = threadIdx.x; i < F_IN * F_OUT; i += blockDim.x) sW[i] = W[i];
    __syncthreads();

    int node = blockIdx.x * blockDim.x + threadIdx.x;
    if (node >= n) return;

    const float* in = x_ext ? x_ext : buf(in_sel);
    const float4* row4 = reinterpret_cast<const float4*>(in) +
                         (long long)node * (F_IN / 4);

    float acc[F_OUT];
#pragma unroll
    for (int j = 0; j < F_OUT; j++) acc[j] = 0.f;

    for (int k4 = 0; k4 < F_IN / 4; k4++) {
        float4 v4 = row4[k4];
        float vv[4] = {v4.x, v4.y, v4.z, v4.w};
#pragma unroll
        for (int u = 0; u < 4; u++) {
            int k = k4 * 4 + u;
#pragma unroll
            for (int j = 0; j < F_OUT; j++)
                acc[j] = fmaf(vv[u], sW[k * F_OUT + j], acc[j]);
        }
    }

    float di = g_dinv[node];
    float4* out4 = reinterpret_cast<float4*>(buf(out_sel)) +
                   (long long)node * (F_OUT / 4);
#pragma unroll
    for (int j4 = 0; j4 < F_OUT / 4; j4++) {
        float o[4];
#pragma unroll
        for (int u = 0; u < 4; u++) {
            float a = acc[j4 * 4 + u];
            if (EPI == 0)      o[u] = a * di;
            else if (EPI == 1) o[u] = fmaxf(a + bout[j4 * 4 + u], 0.f) * di;
            else               o[u] = fmaxf(a + bout[j4 * 4 + u], 0.f);
        }
        out4[j4] = make_float4(o[0], o[1], o[2], o[3]);
    }
}

// ---------------------------------------------------------------------------
// Warp-per-node gather: m = dinv * ( in[d] + sum_{src->d} in[src] )
//   FUSED=false: out = m
//   FUSED=true : out = relu(m + b) * dinv
// 32 lanes = (32/L) edge slots x L float4-lanes; shfl cross-slot reduction.
// ---------------------------------------------------------------------------
template <int F, bool FUSED>
__global__ void k_gather(int in_sel, int out_sel,
                         const float* __restrict__ bias, int n)
{
    constexpr int L = F / 4;          // float4 lanes per node row
    constexpr int SLOTS = 32 / L;     // parallel edge slots per warp

    int node = blockIdx.x * blockDim.y + threadIdx.y;
    if (node >= n) return;
    int lane = threadIdx.x;
    int slot = lane / L;
    int f4   = lane % L;

    const float4* In4 = reinterpret_cast<const float4*>(buf(in_sel));
    int e0 = g_off[node];
    int e1 = g_off[node + 1];

    float4 a = make_float4(0.f, 0.f, 0.f, 0.f);
    if (slot == 0) a = In4[(long long)node * L + f4];   // self-loop term

    for (int e = e0 + slot; e < e1; e += SLOTS) {
        int s = g_csrc[e];
        float4 v = In4[(long long)s * L + f4];
        a.x += v.x; a.y += v.y; a.z += v.z; a.w += v.w;
    }

#pragma unroll
    for (int off = 16; off >= L; off >>= 1) {
        a.x += __shfl_xor_sync(0xffffffffu, a.x, off);
        a.y += __shfl_xor_sync(0xffffffffu, a.y, off);
        a.z += __shfl_xor_sync(0xffffffffu, a.z, off);
        a.w += __shfl_xor_sync(0xffffffffu, a.w, off);
    }

    if (slot == 0) {
        float di = g_dinv[node];
        float4 o;
        o.x = a.x * di; o.y = a.y * di; o.z = a.z * di; o.w = a.w * di;
        if (FUSED) {
            const float4 b4 = reinterpret_cast<const float4*>(bias)[f4];
            o.x = fmaxf(o.x + b4.x, 0.f) * di;
            o.y = fmaxf(o.y + b4.y, 0.f) * di;
            o.z = fmaxf(o.z + b4.z, 0.f) * di;
            o.w = fmaxf(o.w + b4.w, 0.f) * di;
        }
        reinterpret_cast<float4*>(buf(out_sel))[(long long)node * L + f4] = o;
    }
}

// ----------------- pool: segment max over sorted batch ids -----------------
__global__ void k_pool(int in_sel, const int* __restrict__ batch, int n)
{
    int f = threadIdx.x;                              // 0..63
    int chunk = blockIdx.x * blockDim.y + threadIdx.y;
    int n0 = chunk * 16;
    if (n0 >= n) return;
    int n1 = min(n0 + 16, n);
    const float* h = buf(in_sel);

    int curg = batch[n0];
    float m = h[(long long)n0 * 64 + f];
    for (int i = n0 + 1; i < n1; i++) {
        int g = batch[i];
        float v = h[(long long)i * 64 + f];
        if (g != curg) {
            atomicMax((unsigned int*)&g_pool[curg * 64 + f], __float_as_uint(m));
            curg = g;
            m = v;
        } else {
            m = fmaxf(m, v);
        }
    }
    atomicMax((unsigned int*)&g_pool[curg * 64 + f], __float_as_uint(m));
}

// ---------------- fused MLP head: 4 graphs per block ------------------------
// grid = 256 blocks x 256 threads: full-chip parallelism, weight traffic
// 256 x 327KB ~ 84MB (vs 335MB unbatched), no g_zbuf round-trip.
__global__ void k_mlp(const float* __restrict__ W1, const float* __restrict__ b1,
                      const float* __restrict__ W2, const float* __restrict__ b2,
                      float* __restrict__ out)
{
    __shared__ float sp[4 * 64];      // pooled rows for 4 graphs
    __shared__ float sz[4 * 256];     // hidden activations
    int j  = threadIdx.x;             // output feature 0..255
    int g0 = blockIdx.x * 4;

    if (j < 4 * 64) sp[j] = g_pool[g0 * 64 + j];
    __syncthreads();

    float z0 = b1[j], z1 = z0, z2 = z0, z3 = z0;
#pragma unroll 8
    for (int k = 0; k < 64; k++) {
        float w = W1[k * 256 + j];
        z0 = fmaf(sp[0 * 64 + k], w, z0);
        z1 = fmaf(sp[1 * 64 + k], w, z1);
        z2 = fmaf(sp[2 * 64 + k], w, z2);
        z3 = fmaf(sp[3 * 64 + k], w, z3);
    }
    sz[0 * 256 + j] = fmaxf(z0, 0.f);
    sz[1 * 256 + j] = fmaxf(z1, 0.f);
    sz[2 * 256 + j] = fmaxf(z2, 0.f);
    sz[3 * 256 + j] = fmaxf(z3, 0.f);
    __syncthreads();

    float o0 = b2[j], o1 = o0, o2 = o0, o3 = o0;
#pragma unroll 8
    for (int k = 0; k < 256; k++) {
        float w = W2[k * 256 + j];
        o0 = fmaf(sz[0 * 256 + k], w, o0);
        o1 = fmaf(sz[1 * 256 + k], w, o1);
        o2 = fmaf(sz[2 * 256 + k], w, o2);
        o3 = fmaf(sz[3 * 256 + k], w, o3);
    }
    out[(long long)(g0 + 0) * 256 + j] = 1.f / (1.f + expf(-o0));
    out[(long long)(g0 + 1) * 256 + j] = 1.f / (1.f + expf(-o1));
    out[(long long)(g0 + 2) * 256 + j] = 1.f / (1.f + expf(-o2));
    out[(long long)(g0 + 3) * 256 + j] = 1.f / (1.f + expf(-o3));
}

// ------------------------------ launch -------------------------------------
extern "C" void kernel_launch(void* const* d_in, const int* in_sizes, int n_in,
                              void* d_out, int out_size)
{
    const float* x     = (const float*)d_in[0];
    const int*   ei    = (const int*)d_in[1];    // int32 (JAX x64 disabled)
    const int*   batch = (const int*)d_in[2];
    const float* W1 = (const float*)d_in[3];
    const float* b1 = (const float*)d_in[4];
    const float* W2 = (const float*)d_in[5];
    const float* b2 = (const float*)d_in[6];
    const float* W3 = (const float*)d_in[7];
    const float* b3 = (const float*)d_in[8];
    const float* L1w = (const float*)d_in[9];
    const float* L1b = (const float*)d_in[10];
    const float* L2w = (const float*)d_in[11];
    const float* L2b = (const float*)d_in[12];
    float* out = (float*)d_out;

    int N = in_sizes[0] / 128;
    int E = in_sizes[1] / 2;
    int nblk = (N + SCAN_B - 1) / SCAN_B;

    // CSR build (by destination)
    k_zero    <<<(N + 255) / 256, 256>>>(N);
    k_degcount<<<(E + 255) / 256, 256>>>(ei, E);
    k_scan1   <<<nblk, SCAN_B>>>(N);
    k_scan2   <<<1, NBLK_MAX>>>(nblk);
    k_scan3   <<<(N + 255) / 256, 256>>>(N, E);
    k_fill    <<<(E + 255) / 256, 256>>>(ei, E);

    dim3 gb(32, 8);                       // warp-per-node gathers
    int ggrid = (N + 7) / 8;

    // Layer 1:  q0 = (x @ W1) * dinv                       [N,16] -> buf0
    k_transform<128, 16, 0><<<(N + 127) / 128, 128>>>(x, 0, 0, W1, nullptr, N);
    //           q1 = relu(dinv*(q0+Σq0) + b1) * dinv       [N,16] -> buf1
    k_gather<16, true ><<<ggrid, gb>>>(0, 1, b1, N);

    // Layer 2:  m2 = dinv*(q1+Σq1)                         [N,16] -> buf0
    k_gather<16, false><<<ggrid, gb>>>(1, 0, nullptr, N);
    //           q2 = relu(m2 @ W2 + b2) * dinv             [N,32] -> buf1
    k_transform<16, 32, 1><<<(N + 127) / 128, 128>>>(nullptr, 0, 1, W2, b2, N);

    // Layer 3:  m3 = dinv*(q2+Σq2)                         [N,32] -> buf0
    k_gather<32, false><<<ggrid, gb>>>(1, 0, nullptr, N);
    //           h3 = relu(m3 @ W3 + b3)                    [N,64] -> buf1
    k_transform<32, 64, 2><<<(N + 127) / 128, 128>>>(nullptr, 0, 1, W3, b3, N);

    // Pool (batch sorted) + fused MLP head (4 graphs/block)
    { dim3 pb(64, 4); int chunks = (N + 15) / 16;
      k_pool<<<(chunks + 3) / 4, pb>>>(1, batch, N); }
    k_mlp<<<G_NUM / 4, 256>>>(L1w, L1b, L2w, L2b, out);
}

// round 13
// speedup vs baseline: 1.2211x; 1.0498x over previous
#include <cuda_runtime.h>
#include <math.h>

#define N_MAX 100000
#define E_MAX 1600000
#define G_NUM 1024
#define SCAN_B 1024
#define NBLK_MAX 128   // ceil(100000/1024)=98

// ---------------- device scratch (no allocation allowed) -------------------
__device__ __align__(16) float g_B0[(long long)N_MAX * 64]; // ping
__device__ __align__(16) float g_B1[(long long)N_MAX * 64]; // pong
__device__ float g_dinv[N_MAX];
__device__ int   g_deg [N_MAX];
__device__ int   g_tmp [N_MAX];        // block-scan partials
__device__ int   g_off [N_MAX + 1];    // CSR offsets (by dst)
__device__ int   g_bsum[NBLK_MAX];     // block sums for scan
__device__ int   g_pos [E_MAX];        // per-edge rank within dst bucket
__device__ int   g_csrc[E_MAX];        // CSR src ids
__device__ float g_pool[G_NUM * 64];
__device__ float g_zbuf[G_NUM * 256];

__device__ __forceinline__ float* buf(int s) { return s == 0 ? g_B0 : g_B1; }

// ---------------------------- prep -----------------------------------------
__global__ void k_zero(int n) {
    int i = blockIdx.x * blockDim.x + threadIdx.x;
    if (i < n)          g_deg[i]  = 0;
    if (i < G_NUM * 64) g_pool[i] = 0.f;
}

// pass A: one atomic does double duty — counts degree AND returns edge's rank
__global__ void k_pos(const int* __restrict__ ei, int E) {
    int e = blockIdx.x * blockDim.x + threadIdx.x;
    if (e >= E) return;
    g_pos[e] = atomicAdd(&g_deg[ei[E + e]], 1);
}

// ------------------------- 3-kernel exclusive scan --------------------------
__global__ void k_scan1(int n) {
    __shared__ int s[SCAN_B];
    int t = threadIdx.x;
    int i = blockIdx.x * SCAN_B + t;
    int v = (i < n) ? g_deg[i] : 0;
    s[t] = v;
    __syncthreads();
#pragma unroll
    for (int d = 1; d < SCAN_B; d <<= 1) {
        int x = (t >= d) ? s[t - d] : 0;
        __syncthreads();
        s[t] += x;
        __syncthreads();
    }
    if (i < n) g_tmp[i] = s[t];                 // inclusive
    if (t == SCAN_B - 1) g_bsum[blockIdx.x] = s[t];
}

__global__ void k_scan2(int nblk) {
    __shared__ int s[NBLK_MAX];
    int t = threadIdx.x;
    int v = (t < nblk) ? g_bsum[t] : 0;
    s[t] = v;
    __syncthreads();
#pragma unroll
    for (int d = 1; d < NBLK_MAX; d <<= 1) {
        int x = (t >= d) ? s[t - d] : 0;
        __syncthreads();
        s[t] += x;
        __syncthreads();
    }
    if (t < nblk) g_bsum[t] = s[t] - v;         // exclusive
}

__global__ void k_scan3(int n, int E) {
    int i = blockIdx.x * blockDim.x + threadIdx.x;
    if (i < n) {
        int deg = g_deg[i];
        g_off[i] = g_tmp[i] - deg + g_bsum[i / SCAN_B];  // exclusive
        g_dinv[i] = rsqrtf((float)(deg + 1));            // +1 self loop
    }
    if (i == 0) g_off[n] = E;
}

// pass B: atomic-free placement
__global__ void k_place(const int* __restrict__ ei, int E) {
    int e = blockIdx.x * blockDim.x + threadIdx.x;
    if (e >= E) return;
    int s = ei[e];
    int d = ei[E + e];
    g_csrc[g_off[d] + g_pos[e]] = s;
}

// ---------------------------------------------------------------------------
// Node transform: acc = in @ W, then epilogue:
//   EPI 0: out = acc * dinv                      (pre-scale for next gather)
//   EPI 1: out = relu(acc + b) * dinv            (activation + pre-scale)
//   EPI 2: out = relu(acc + b)                   (final features for pool)
// ---------------------------------------------------------------------------
template <int F_IN, int F_OUT, int EPI>
__global__ void k_transform(const float* __restrict__ x_ext, int in_sel, int out_sel,
                            const float* __restrict__ W,
                            const float* __restrict__ bout, int n)
{
    __shared__ float sW[F_IN * F_OUT];
    for (int i = threadIdx.x; i < F_IN * F_OUT; i += blockDim.x) sW[i] = W[i];
    __syncthreads();

    int node = blockIdx.x * blockDim.x + threadIdx.x;
    if (node >= n) return;

    const float* in = x_ext ? x_ext : buf(in_sel);
    const float4* row4 = reinterpret_cast<const float4*>(in) +
                         (long long)node * (F_IN / 4);

    float acc[F_OUT];
#pragma unroll
    for (int j = 0; j < F_OUT; j++) acc[j] = 0.f;

    for (int k4 = 0; k4 < F_IN / 4; k4++) {
        float4 v4 = row4[k4];
        float vv[4] = {v4.x, v4.y, v4.z, v4.w};
#pragma unroll
        for (int u = 0; u < 4; u++) {
            int k = k4 * 4 + u;
#pragma unroll
            for (int j = 0; j < F_OUT; j++)
                acc[j] = fmaf(vv[u], sW[k * F_OUT + j], acc[j]);
        }
    }

    float di = g_dinv[node];
    float4* out4 = reinterpret_cast<float4*>(buf(out_sel)) +
                   (long long)node * (F_OUT / 4);
#pragma unroll
    for (int j4 = 0; j4 < F_OUT / 4; j4++) {
        float o[4];
#pragma unroll
        for (int u = 0; u < 4; u++) {
            float a = acc[j4 * 4 + u];
            if (EPI == 0)      o[u] = a * di;
            else if (EPI == 1) o[u] = fmaxf(a + bout[j4 * 4 + u], 0.f) * di;
            else               o[u] = fmaxf(a + bout[j4 * 4 + u], 0.f);
        }
        out4[j4] = make_float4(o[0], o[1], o[2], o[3]);
    }
}

// ---------------------------------------------------------------------------
// Warp-per-node gather: m = dinv * ( in[d] + sum_{src->d} in[src] )
//   FUSED=false: out = m
//   FUSED=true : out = relu(m + b) * dinv
// 32 lanes = (32/L) edge slots x L float4-lanes; edge loop unrolled x2 so two
// independent row loads are in flight per slot; shfl cross-slot reduction.
// ---------------------------------------------------------------------------
template <int F, bool FUSED>
__global__ void k_gather(int in_sel, int out_sel,
                         const float* __restrict__ bias, int n)
{
    constexpr int L = F / 4;          // float4 lanes per node row
    constexpr int SLOTS = 32 / L;     // parallel edge slots per warp

    int node = blockIdx.x * blockDim.y + threadIdx.y;
    if (node >= n) return;
    int lane = threadIdx.x;
    int slot = lane / L;
    int f4   = lane % L;

    const float4* In4 = reinterpret_cast<const float4*>(buf(in_sel));
    int e0 = g_off[node];
    int e1 = g_off[node + 1];

    float4 a = make_float4(0.f, 0.f, 0.f, 0.f);
    float4 b = make_float4(0.f, 0.f, 0.f, 0.f);
    if (slot == 0) a = In4[(long long)node * L + f4];   // self-loop term

    int e = e0 + slot;
    for (; e + SLOTS < e1; e += 2 * SLOTS) {
        int s0 = g_csrc[e];
        int s1 = g_csrc[e + SLOTS];
        float4 v0 = In4[(long long)s0 * L + f4];
        float4 v1 = In4[(long long)s1 * L + f4];
        a.x += v0.x; a.y += v0.y; a.z += v0.z; a.w += v0.w;
        b.x += v1.x; b.y += v1.y; b.z += v1.z; b.w += v1.w;
    }
    if (e < e1) {
        int s0 = g_csrc[e];
        float4 v0 = In4[(long long)s0 * L + f4];
        a.x += v0.x; a.y += v0.y; a.z += v0.z; a.w += v0.w;
    }
    a.x += b.x; a.y += b.y; a.z += b.z; a.w += b.w;

#pragma unroll
    for (int off = 16; off >= L; off >>= 1) {
        a.x += __shfl_xor_sync(0xffffffffu, a.x, off);
        a.y += __shfl_xor_sync(0xffffffffu, a.y, off);
        a.z += __shfl_xor_sync(0xffffffffu, a.z, off);
        a.w += __shfl_xor_sync(0xffffffffu, a.w, off);
    }

    if (slot == 0) {
        float di = g_dinv[node];
        float4 o;
        o.x = a.x * di; o.y = a.y * di; o.z = a.z * di; o.w = a.w * di;
        if (FUSED) {
            const float4 b4 = reinterpret_cast<const float4*>(bias)[f4];
            o.x = fmaxf(o.x + b4.x, 0.f) * di;
            o.y = fmaxf(o.y + b4.y, 0.f) * di;
            o.z = fmaxf(o.z + b4.z, 0.f) * di;
            o.w = fmaxf(o.w + b4.w, 0.f) * di;
        }
        reinterpret_cast<float4*>(buf(out_sel))[(long long)node * L + f4] = o;
    }
}

// ----------------- pool: segment max over sorted batch ids -----------------
__global__ void k_pool(int in_sel, const int* __restrict__ batch, int n)
{
    int f = threadIdx.x;                              // 0..63
    int chunk = blockIdx.x * blockDim.y + threadIdx.y;
    int n0 = chunk * 16;
    if (n0 >= n) return;
    int n1 = min(n0 + 16, n);
    const float* h = buf(in_sel);

    int curg = batch[n0];
    float m = h[(long long)n0 * 64 + f];
    for (int i = n0 + 1; i < n1; i++) {
        int g = batch[i];
        float v = h[(long long)i * 64 + f];
        if (g != curg) {
            atomicMax((unsigned int*)&g_pool[curg * 64 + f], __float_as_uint(m));
            curg = g;
            m = v;
        } else {
            m = fmaxf(m, v);
        }
    }
    atomicMax((unsigned int*)&g_pool[curg * 64 + f], __float_as_uint(m));
}

// ----------------------------- MLP head (R9 shape) --------------------------
__global__ void k_mlp1(const float* __restrict__ W, const float* __restrict__ b)
{
    __shared__ float sp[64];
    int g = blockIdx.x, j = threadIdx.x;   // 256 threads
    if (j < 64) sp[j] = g_pool[g * 64 + j];
    __syncthreads();
    float acc = b[j];
#pragma unroll
    for (int k = 0; k < 64; k++) acc = fmaf(sp[k], W[k * 256 + j], acc);
    g_zbuf[g * 256 + j] = fmaxf(acc, 0.f);
}

__global__ void k_mlp2(const float* __restrict__ W, const float* __restrict__ b,
                       float* __restrict__ out)
{
    __shared__ float sz[256];
    int g = blockIdx.x, j = threadIdx.x;   // 256 threads
    sz[j] = g_zbuf[g * 256 + j];
    __syncthreads();
    float acc = b[j];
#pragma unroll 8
    for (int k = 0; k < 256; k++) acc = fmaf(sz[k], W[k * 256 + j], acc);
    out[g * 256 + j] = 1.f / (1.f + expf(-acc));
}

// ------------------------------ launch -------------------------------------
extern "C" void kernel_launch(void* const* d_in, const int* in_sizes, int n_in,
                              void* d_out, int out_size)
{
    const float* x     = (const float*)d_in[0];
    const int*   ei    = (const int*)d_in[1];    // int32 (JAX x64 disabled)
    const int*   batch = (const int*)d_in[2];
    const float* W1 = (const float*)d_in[3];
    const float* b1 = (const float*)d_in[4];
    const float* W2 = (const float*)d_in[5];
    const float* b2 = (const float*)d_in[6];
    const float* W3 = (const float*)d_in[7];
    const float* b3 = (const float*)d_in[8];
    const float* L1w = (const float*)d_in[9];
    const float* L1b = (const float*)d_in[10];
    const float* L2w = (const float*)d_in[11];
    const float* L2b = (const float*)d_in[12];
    float* out = (float*)d_out;

    int N = in_sizes[0] / 128;
    int E = in_sizes[1] / 2;
    int nblk = (N + SCAN_B - 1) / SCAN_B;

    // CSR build (by destination): rank-then-place, single atomic pass
    k_zero  <<<(N + 255) / 256, 256>>>(N);
    k_pos   <<<(E + 255) / 256, 256>>>(ei, E);
    k_scan1 <<<nblk, SCAN_B>>>(N);
    k_scan2 <<<1, NBLK_MAX>>>(nblk);
    k_scan3 <<<(N + 255) / 256, 256>>>(N, E);
    k_place <<<(E + 255) / 256, 256>>>(ei, E);

    dim3 gb(32, 8);                       // warp-per-node gathers
    int ggrid = (N + 7) / 8;

    // Layer 1:  q0 = (x @ W1) * dinv                       [N,16] -> buf0
    k_transform<128, 16, 0><<<(N + 127) / 128, 128>>>(x, 0, 0, W1, nullptr, N);
    //           q1 = relu(dinv*(q0+Σq0) + b1) * dinv       [N,16] -> buf1
    k_gather<16, true ><<<ggrid, gb>>>(0, 1, b1, N);

    // Layer 2:  m2 = dinv*(q1+Σq1)                         [N,16] -> buf0
    k_gather<16, false><<<ggrid, gb>>>(1, 0, nullptr, N);
    //           q2 = relu(m2 @ W2 + b2) * dinv             [N,32] -> buf1
    k_transform<16, 32, 1><<<(N + 127) / 128, 128>>>(nullptr, 0, 1, W2, b2, N);

    // Layer 3:  m3 = dinv*(q2+Σq2)                         [N,32] -> buf0
    k_gather<32, false><<<ggrid, gb>>>(1, 0, nullptr, N);
    //           h3 = relu(m3 @ W3 + b3)                    [N,64] -> buf1
    k_transform<32, 64, 2><<<(N + 127) / 128, 128>>>(nullptr, 0, 1, W3, b3, N);

    // Pool (batch sorted) + MLP head
    { dim3 pb(64, 4); int chunks = (N + 15) / 16;
      k_pool<<<(chunks + 3) / 4, pb>>>(1, batch, N); }
    k_mlp1<<<G_NUM, 256>>>(L1w, L1b);
    k_mlp2<<<G_NUM, 256>>>(L2w, L2b, out);
}